// round 8
// baseline (speedup 1.0000x reference)
#include <cuda_runtime.h>
#include <cuda_bf16.h>
#include <cstdint>

// Problem constants (shape fixed by dataset: img [64, 3, 512, 512])
constexpr int NCH = 192;           // 64*3 channels
constexpr int P   = 262144;        // 512*512 pixels / channel
constexpr int NB  = 256;           // bins

// Pipeline structure: 24 channels in flight, 8 sequential iterations.
constexpr int CONC  = 24;              // concurrent channels
constexpr int ITERS = NCH / CONC;      // 8
constexpr int HPC   = 8;               // hist blocks per channel
constexpr int APC   = 16;              // apply blocks per channel
constexpr int NHIST  = CONC * HPC;     // 192
constexpr int NAPPLY = CONC * APC;     // 384
constexpr int NBLK   = NHIST + NAPPLY; // 576 <= 148*4 -> fully co-resident

// Scratch — __device__ globals. All zero at load; kernel restores zeros
// itself each run, so graph replays start clean with no cleanup launch.
__device__ int   g_hist [NCH * NB];
__device__ float g_lut  [NCH * NB];
__device__ int   g_cdone[NCH];     // hist-blocks-done per channel
__device__ int   g_adone[NCH];     // apply-blocks-passed-spin per channel
__device__ int   g_flag [NCH];     // LUT-ready flag per channel

// ---------------------------------------------------------------------------
// Fused persistent kernel, role-specialized per block:
//  - 192 hist blocks: stream input (read-bound), per-warp smem hists, publish
//    per channel; the LAST hist block of a channel computes the LUT, restores
//    g_hist/g_cdone to zero, and raises g_flag[c].
//  - 384 apply blocks: spin per channel on g_flag, load LUT, translate+write
//    (write-bound). The last apply block to pass the spin restores
//    g_flag/g_adone to zero.
// Read stream and write stream overlap across the whole kernel.
// ---------------------------------------------------------------------------
__global__ void __launch_bounds__(256, 4) fused_kernel(const float* __restrict__ in,
                                                       float* __restrict__ out) {
    __shared__ int sh[8 * NB];     // hist: 8 warp-hists / LUT build. apply: LUT.
    const int tid = threadIdx.x;
    const int bid = blockIdx.x;

    if (bid < NHIST) {
        // ---------------- HIST ROLE ----------------
        const int cg = bid / HPC;          // concurrent-channel lane [0,24)
        const int h  = bid % HPC;          // slice within channel
        int* const myh = &sh[(tid >> 5) * NB];
        __shared__ int s_ticket;

        for (int g = 0; g < ITERS; g++) {
            const int c = g * CONC + cg;
            for (int i = tid; i < 8 * NB; i += 256) sh[i] = 0;
            __syncthreads();

            // 8192 float4 per slice, 4 loads in flight.
            const float4* bi =
                reinterpret_cast<const float4*>(in + (size_t)c * P) + h * (P / 4 / HPC);
            for (int i = tid; i < P / 4 / HPC; i += 1024) {
                float4 a = bi[i];
                float4 b = bi[i + 256];
                float4 d = bi[i + 512];
                float4 e = bi[i + 768];
                atomicAdd(&myh[(int)a.x], 1); atomicAdd(&myh[(int)a.y], 1);
                atomicAdd(&myh[(int)a.z], 1); atomicAdd(&myh[(int)a.w], 1);
                atomicAdd(&myh[(int)b.x], 1); atomicAdd(&myh[(int)b.y], 1);
                atomicAdd(&myh[(int)b.z], 1); atomicAdd(&myh[(int)b.w], 1);
                atomicAdd(&myh[(int)d.x], 1); atomicAdd(&myh[(int)d.y], 1);
                atomicAdd(&myh[(int)d.z], 1); atomicAdd(&myh[(int)d.w], 1);
                atomicAdd(&myh[(int)e.x], 1); atomicAdd(&myh[(int)e.y], 1);
                atomicAdd(&myh[(int)e.z], 1); atomicAdd(&myh[(int)e.w], 1);
            }
            __syncthreads();

            // Reduce 8 warp-hists -> global (L2 atomics).
            int s = 0;
#pragma unroll
            for (int k = 0; k < 8; k++) s += sh[k * NB + tid];
            if (s) atomicAdd(&g_hist[c * NB + tid], s);
            __threadfence();               // publish before counting done
            __syncthreads();
            if (tid == 0) s_ticket = atomicAdd(&g_cdone[c], 1);
            __syncthreads();

            if (s_ticket == HPC - 1) {
                // -------- LUT producer for channel c --------
                __threadfence();           // acquire all hist contributions
                int*  H  = sh;
                int*  CS = sh + NB;
                int*  RD = sh + 2 * NB;
                const int hv = __ldcg(&g_hist[c * NB + tid]);
                H[tid]  = hv;
                CS[tid] = hv;
                __syncthreads();
#pragma unroll
                for (int off = 1; off < NB; off <<= 1) {   // inclusive scan
                    int v = (tid >= off) ? CS[tid - off] : 0;
                    __syncthreads();
                    CS[tid] += v;
                    __syncthreads();
                }
                RD[tid] = hv ? tid : -1;                   // last nonzero bin
                __syncthreads();
#pragma unroll
                for (int sdx = 128; sdx > 0; sdx >>= 1) {
                    if (tid < sdx) RD[tid] = max(RD[tid], RD[tid + sdx]);
                    __syncthreads();
                }
                const int last_val = H[RD[0]];
                const int step = (P - last_val) / 255;     // exact PIL math
                const int safe = step > 0 ? step : 1;
                const int prev = tid ? CS[tid - 1] : 0;
                int lv = (prev + step / 2) / safe;
                lv = min(max(lv, 0), 255);
                if (step == 0) lv = tid;   // passthrough as identity LUT
                g_lut[c * NB + tid] = (float)lv;

                g_hist[c * NB + tid] = 0;  // restore for next graph replay
                if (tid == 0) g_cdone[c] = 0;
                __threadfence();           // LUT + restores visible first
                __syncthreads();
                if (tid == 0) *(volatile int*)&g_flag[c] = 1;
            }
        }
    } else {
        // ---------------- APPLY ROLE ----------------
        const int a  = bid - NHIST;
        const int cg = a / APC;            // concurrent-channel lane [0,24)
        const int j  = a % APC;            // slice within channel
        float* LUT = reinterpret_cast<float*>(sh);
        __shared__ int s_ticket;

        for (int g = 0; g < ITERS; g++) {
            const int c = g * CONC + cg;

            if (tid == 0) {
                while (*(volatile int*)&g_flag[c] == 0) __nanosleep(64);
                s_ticket = atomicAdd(&g_adone[c], 1);
            }
            __syncthreads();
            __threadfence();
            LUT[tid] = __ldcg(&g_lut[c * NB + tid]);
            __syncthreads();
            // Last apply block past the spin restores flag/counter.
            if (s_ticket == APC - 1 && tid == 0) {
                g_adone[c] = 0;
                *(volatile int*)&g_flag[c] = 0;
            }

            // 4096 float4 per slice, 4 loads in flight; __ldcs: lines are dead
            // after this read. __stcs: keep output stream out of L2.
            const float4* bi =
                reinterpret_cast<const float4*>(in + (size_t)c * P) + j * (P / 4 / APC);
            float4* bo =
                reinterpret_cast<float4*>(out + (size_t)c * P) + j * (P / 4 / APC);
            for (int i = tid; i < P / 4 / APC; i += 1024) {
                float4 x = __ldcs(&bi[i]);
                float4 y = __ldcs(&bi[i + 256]);
                float4 z = __ldcs(&bi[i + 512]);
                float4 w = __ldcs(&bi[i + 768]);
                float4 o;
                o.x = LUT[(int)x.x]; o.y = LUT[(int)x.y];
                o.z = LUT[(int)x.z]; o.w = LUT[(int)x.w];
                __stcs(&bo[i], o);
                o.x = LUT[(int)y.x]; o.y = LUT[(int)y.y];
                o.z = LUT[(int)y.z]; o.w = LUT[(int)y.w];
                __stcs(&bo[i + 256], o);
                o.x = LUT[(int)z.x]; o.y = LUT[(int)z.y];
                o.z = LUT[(int)z.z]; o.w = LUT[(int)z.w];
                __stcs(&bo[i + 512], o);
                o.x = LUT[(int)w.x]; o.y = LUT[(int)w.y];
                o.z = LUT[(int)w.z]; o.w = LUT[(int)w.w];
                __stcs(&bo[i + 768], o);
            }
            __syncthreads();               // smem (LUT) reuse next iteration
        }
    }
}

// ---------------------------------------------------------------------------
extern "C" void kernel_launch(void* const* d_in, const int* in_sizes, int n_in,
                              void* d_out, int out_size) {
    const float* img = (const float*)d_in[0];
    float* out = (float*)d_out;
    fused_kernel<<<NBLK, 256>>>(img, out);
}